// round 5
// baseline (speedup 1.0000x reference)
#include <cuda_runtime.h>
#include <math.h>

#define IDIM 128
#define HDIM 1024
#define NITER 4
#define NTOK 2048
#define TOK_PER_BLK 8
#define NBLK (NTOK / TOK_PER_BLK)   // 256
#define NTHREADS 256
#define XPAD 384            // padded x_res (data at [127,254], zeros elsewhere)
#define WST_STRIDE 33       // float4 stride per staged weight row (conflict-free)
#define HROW 264            // h row stride in floats (16B-aligned rows)

typedef unsigned long long ull;

__device__ float g_psum[NBLK];
__device__ float g_pcnt[NBLK];

// ---- packed fp32x2 helpers (SASS FFMA2 — only reachable via PTX) ----
__device__ __forceinline__ ull pk(float lo, float hi) {
    ull r; asm("mov.b64 %0, {%1, %2};" : "=l"(r) : "f"(lo), "f"(hi)); return r;
}
__device__ __forceinline__ void fma2(ull& acc, ull a, ull b) {
    asm("fma.rn.f32x2 %0, %1, %2, %3;" : "=l"(acc) : "l"(a), "l"(b), "l"(acc));
}
__device__ __forceinline__ float2 upk(ull v) {
    float2 r; asm("mov.b64 {%0, %1}, %2;" : "=f"(r.x), "=f"(r.y) : "l"(v)); return r;
}

struct __align__(16) Smem {
    float4 wst[IDIM * WST_STRIDE];     // 128 rows x 33 float4 = 67584 B
    float  xp[TOK_PER_BLK][XPAD];      // 12288 B
    float  xa[TOK_PER_BLK][IDIM];      // x_attn, token-major, 4096 B
    float  h[TOK_PER_BLK][HROW];       // hidden, token-major, 8448 B
    float  yres[TOK_PER_BLK][IDIM];    // 4096 B
    float  red[8];
    float  red2[8];
    unsigned char ymask[TOK_PER_BLK][IDIM];  // 1024 B
};

extern __shared__ unsigned char smem_raw[];

__global__ void __launch_bounds__(NTHREADS, 2)
net_main_kernel(const float* __restrict__ x, const float* __restrict__ y,
                const float* __restrict__ w1, const float* __restrict__ b1,
                const float* __restrict__ w2, const float* __restrict__ b2)
{
    Smem& sm = *reinterpret_cast<Smem*>(smem_raw);
    const int tid  = threadIdx.x;
    const int lane = tid & 31;
    const int wid  = tid >> 5;
    const int blk  = blockIdx.x;
    const int tok0 = blk * TOK_PER_BLK;

    // ---- zero padded x buffer ----
    for (int e = tid; e < TOK_PER_BLK * XPAD; e += NTHREADS)
        (&sm.xp[0][0])[e] = 0.f;
    __syncthreads();

    // ---- load x, y, mask; count unmasked ----
    float cnt = 0.f;
    for (int e = tid; e < TOK_PER_BLK * IDIM; e += NTHREADS) {
        int m = e >> 7, d = e & 127;
        sm.xp[m][127 + d] = x[(tok0 + m) * IDIM + d];
        float yv = y[(tok0 + m) * IDIM + d];
        sm.yres[m][d] = yv;
        unsigned char msk = (yv == 10000.0f) ? 1 : 0;
        sm.ymask[m][d] = msk;
        cnt += msk ? 0.f : 1.f;
    }

    float sqacc = 0.f;
    const int o = tid & 127;    // channel within chunk (B) / output channel (C)
    const int g = tid >> 7;     // token group: tokens 4g..4g+3

    for (int it = 0; it < NITER; ++it) {
        __syncthreads();   // yres/xp stable for phase A

        // ================= Phase A: per-warp token pipeline =================
        {
            const int m = wid;
            float* xpm = sm.xp[m];
            const float*  ym  = sm.yres[m];
            const float4* xp4 = reinterpret_cast<const float4*>(xpm);
            const float4* ym4 = reinterpret_cast<const float4*>(ym);

            // ||y_res||
            float ny2 = 0.f;
            #pragma unroll
            for (int j = 0; j < 4; ++j) { float v = ym[lane + 32 * j]; ny2 += v * v; }
            #pragma unroll
            for (int off = 16; off; off >>= 1) ny2 += __shfl_xor_sync(~0u, ny2, off);
            float ny = sqrtf(ny2);

            // banded correlation, FFMA2 over (even-d, odd-d) pairs.
            // lane handles shifts s = 4*lane + 128*b + j, j=0..3
            ull num2[8], dn2[8];
            #pragma unroll
            for (int k = 0; k < 8; ++k) { num2[k] = 0ull; dn2[k] = 0ull; }
            #pragma unroll
            for (int b = 0; b < 2; ++b) {
                int q0 = lane + 32 * b;            // float4 base index (s0/4)
                float4 xcur = xp4[q0];
                #pragma unroll 8
                for (int d4 = 0; d4 < 32; ++d4) {
                    float4 yv  = ym4[d4];
                    float4 xnx = xp4[q0 + d4 + 1];
                    ull ypA = pk(yv.x, yv.y);      // dims (0,1) of this d4
                    ull ypB = pk(yv.z, yv.w);      // dims (2,3)
                    ull p01 = pk(xcur.x, xcur.y);
                    ull p12 = pk(xcur.y, xcur.z);
                    ull p23 = pk(xcur.z, xcur.w);
                    ull p34 = pk(xcur.w, xnx.x);
                    ull p45 = pk(xnx.x,  xnx.y);
                    ull p56 = pk(xnx.y,  xnx.z);
                    int k0 = 4 * b;
                    // j=0: x pairs (0,1),(2,3)
                    fma2(num2[k0+0], ypA, p01); fma2(dn2[k0+0], p01, p01);
                    fma2(num2[k0+0], ypB, p23); fma2(dn2[k0+0], p23, p23);
                    // j=1: (1,2),(3,4)
                    fma2(num2[k0+1], ypA, p12); fma2(dn2[k0+1], p12, p12);
                    fma2(num2[k0+1], ypB, p34); fma2(dn2[k0+1], p34, p34);
                    // j=2: (2,3),(4,5)
                    fma2(num2[k0+2], ypA, p23); fma2(dn2[k0+2], p23, p23);
                    fma2(num2[k0+2], ypB, p45); fma2(dn2[k0+2], p45, p45);
                    // j=3: (3,4),(5,6)
                    fma2(num2[k0+3], ypA, p34); fma2(dn2[k0+3], p34, p34);
                    fma2(num2[k0+3], ypB, p56); fma2(dn2[k0+3], p56, p56);
                    xcur = xnx;
                }
            }

            // per-lane first-max (ascending s within lane), then warp first-max
            float best = -INFINITY; int bs = 0x7fffffff;
            #pragma unroll
            for (int b = 0; b < 2; ++b)
            #pragma unroll
            for (int j = 0; j < 4; ++j) {
                int s = 4 * lane + 128 * b + j;
                if (s < 255) {
                    int kk = 4 * b + j;
                    float2 nn = upk(num2[kk]);
                    float2 qq = upk(dn2[kk]);
                    float numv = nn.x + nn.y;
                    float dnv  = qq.x + qq.y;
                    float den = ny * sqrtf(dnv);
                    float sim = (den == 0.f) ? 0.f : numv / den;
                    if (sim > best) { best = sim; bs = s; }
                }
            }
            #pragma unroll
            for (int off = 16; off; off >>= 1) {
                float ob = __shfl_xor_sync(~0u, best, off);
                int   os = __shfl_xor_sync(~0u, bs,   off);
                if (ob > best || (ob == best && os < bs)) { best = ob; bs = os; }
            }
            const int idx = bs;

            // softmax attention: z = x_aug * y_res
            float xav[4], z[4];
            float zmax = -INFINITY;
            #pragma unroll
            for (int j = 0; j < 4; ++j) {
                int d = lane + 32 * j;
                xav[j] = xpm[idx + d];
                z[j]   = xav[j] * ym[d];
                zmax   = fmaxf(zmax, z[j]);
            }
            #pragma unroll
            for (int off = 16; off; off >>= 1) zmax = fmaxf(zmax, __shfl_xor_sync(~0u, zmax, off));
            float es = 0.f, e[4];
            #pragma unroll
            for (int j = 0; j < 4; ++j) { e[j] = expf(z[j] - zmax); es += e[j]; }
            #pragma unroll
            for (int off = 16; off; off >>= 1) es += __shfl_xor_sync(~0u, es, off);
            #pragma unroll
            for (int j = 0; j < 4; ++j) {
                int d = lane + 32 * j;
                sm.xa[m][d] = xav[j] * (e[j] / es);   // x_attn, token-major
            }
            __syncwarp();
            // reverse shift: x_res[d] -= x_attn[d + 127 - idx]
            #pragma unroll
            for (int j = 0; j < 4; ++j) {
                int d = lane + 32 * j;
                int src = d + 127 - idx;
                float xe = (src >= 0 && src < 128) ? sm.xa[m][src] : 0.f;
                xpm[127 + d] -= xe;
            }
        }
        __syncthreads();   // xa ready; xp updates done

        // ================= Phase B: h = x_attn @ W1_slice^T + b1 =================
        const float4* xa4 = reinterpret_cast<const float4*>(&sm.xa[0][0]);
        for (int chunk = 0; chunk < 2; ++chunk) {
            const float4* wg = reinterpret_cast<const float4*>(
                w1 + (size_t)(it * 256 + chunk * 128) * IDIM);
            #pragma unroll
            for (int r = 0; r < 16; ++r) {
                int j   = tid + r * 256;
                int row = j >> 5;
                int c4  = j & 31;
                sm.wst[row * WST_STRIDE + c4] = wg[j];
            }
            __syncthreads();

            float bv = b1[it * 256 + chunk * 128 + o];
            ull acc[4];
            acc[0] = pk(bv, 0.f); acc[1] = pk(bv, 0.f);
            acc[2] = pk(bv, 0.f); acc[3] = pk(bv, 0.f);
            const float4* wrow = &sm.wst[o * WST_STRIDE];
            #pragma unroll 8
            for (int d4 = 0; d4 < 32; ++d4) {
                float4 w4 = wrow[d4];
                ull w01 = pk(w4.x, w4.y);
                ull w23 = pk(w4.z, w4.w);
                #pragma unroll
                for (int t = 0; t < 4; ++t) {
                    float4 xv = xa4[(4 * g + t) * 32 + d4];
                    fma2(acc[t], w01, pk(xv.x, xv.y));
                    fma2(acc[t], w23, pk(xv.z, xv.w));
                }
            }
            #pragma unroll
            for (int t = 0; t < 4; ++t) {
                float2 a = upk(acc[t]);
                sm.h[4 * g + t][chunk * 128 + o] = a.x + a.y;
            }
            __syncthreads();
        }

        // ================= Phase C: y_ele = h @ W2_slice^T + b2 =================
        const float4* h4 = reinterpret_cast<const float4*>(&sm.h[0][0]);
        float b2v = b2[o];
        ull accc[4];
        accc[0] = pk(b2v, 0.f); accc[1] = pk(b2v, 0.f);
        accc[2] = pk(b2v, 0.f); accc[3] = pk(b2v, 0.f);
        for (int chunk = 0; chunk < 2; ++chunk) {
            const float4* wg2 = reinterpret_cast<const float4*>(w2);
            #pragma unroll
            for (int r = 0; r < 16; ++r) {
                int j   = tid + r * 256;
                int row = j >> 5;
                int c4  = j & 31;
                sm.wst[row * WST_STRIDE + c4] =
                    wg2[(size_t)row * (HDIM / 4) + it * 64 + chunk * 32 + c4];
            }
            __syncthreads();

            const float4* wrow = &sm.wst[o * WST_STRIDE];
            #pragma unroll 8
            for (int c4 = 0; c4 < 32; ++c4) {
                float4 w4 = wrow[c4];
                ull w01 = pk(w4.x, w4.y);
                ull w23 = pk(w4.z, w4.w);
                #pragma unroll
                for (int t = 0; t < 4; ++t) {
                    float4 hv = h4[(4 * g + t) * (HROW / 4) + chunk * 32 + c4];
                    fma2(accc[t], w01, pk(hv.x, hv.y));
                    fma2(accc[t], w23, pk(hv.z, hv.w));
                }
            }
            if (chunk == 0) __syncthreads();   // before restaging wst
        }

        // ---- masked squared error + y_res update ----
        #pragma unroll
        for (int t = 0; t < 4; ++t) {
            int m = 4 * g + t;
            float2 c2 = upk(accc[t]);
            float ye = c2.x + c2.y;
            float yr = sm.yres[m][o];
            if (!sm.ymask[m][o]) { float dd = ye - yr; sqacc += dd * dd; }
            sm.yres[m][o] = yr - ye;
        }
        // next-iteration top __syncthreads orders these writes (and wst reads)
        // before phase A / restaging
    }

    // ---- block reduction ----
    #pragma unroll
    for (int off = 16; off; off >>= 1) {
        sqacc += __shfl_xor_sync(~0u, sqacc, off);
        cnt   += __shfl_xor_sync(~0u, cnt,   off);
    }
    if (lane == 0) { sm.red[wid] = sqacc; sm.red2[wid] = cnt; }
    __syncthreads();
    if (tid == 0) {
        float s = 0.f, c = 0.f;
        #pragma unroll
        for (int w = 0; w < 8; ++w) { s += sm.red[w]; c += sm.red2[w]; }
        g_psum[blk] = s;
        g_pcnt[blk] = c;
    }
}

__global__ void net_final_kernel(float* __restrict__ out)
{
    __shared__ float ss[NBLK];
    __shared__ float sc[NBLK];
    int t = threadIdx.x;
    ss[t] = g_psum[t];
    sc[t] = g_pcnt[t];
    __syncthreads();
    for (int off = 128; off; off >>= 1) {
        if (t < off) { ss[t] += ss[t + off]; sc[t] += sc[t + off]; }
        __syncthreads();
    }
    if (t == 0) out[0] = ss[0] / (4.0f * sc[0]);
}

extern "C" void kernel_launch(void* const* d_in, const int* in_sizes, int n_in,
                              void* d_out, int out_size)
{
    (void)in_sizes; (void)n_in; (void)out_size;
    const float* x  = (const float*)d_in[0];
    const float* y  = (const float*)d_in[1];
    const float* w1 = (const float*)d_in[2];
    const float* b1 = (const float*)d_in[3];
    const float* w2 = (const float*)d_in[4];
    const float* b2 = (const float*)d_in[5];
    float* out = (float*)d_out;

    cudaFuncSetAttribute(net_main_kernel,
                         cudaFuncAttributeMaxDynamicSharedMemorySize,
                         (int)sizeof(Smem));
    net_main_kernel<<<NBLK, NTHREADS, sizeof(Smem)>>>(x, y, w1, b1, w2, b2);
    net_final_kernel<<<1, NBLK>>>(out);
}

// round 6
// speedup vs baseline: 1.0683x; 1.0683x over previous
#include <cuda_runtime.h>
#include <math.h>

#define IDIM 128
#define HDIM 1024
#define NITER 4
#define NTOK 2048
#define TOK_PER_BLK 8
#define NBLK (NTOK / TOK_PER_BLK)   // 256
#define NTHREADS 256
#define XPAD 384            // padded x_res (data at [127,254], zeros elsewhere)
#define WST_STRIDE 33       // float4 stride per staged weight row (conflict-free)
#define HROW 264            // h row stride in floats (16B-aligned rows)

typedef unsigned long long ull;

__device__ float g_psum[NBLK];
__device__ float g_pcnt[NBLK];

// ---- packed fp32x2 helpers ----
__device__ __forceinline__ ull pk(float lo, float hi) {
    ull r; asm("mov.b64 %0, {%1, %2};" : "=l"(r) : "f"(lo), "f"(hi)); return r;
}
__device__ __forceinline__ void fma2(ull& acc, ull a, ull b) {
    asm("fma.rn.f32x2 %0, %1, %2, %3;" : "=l"(acc) : "l"(a), "l"(b), "l"(acc));
}
__device__ __forceinline__ float2 upk(ull v) {
    float2 r; asm("mov.b64 {%0, %1}, %2;" : "=f"(r.x), "=f"(r.y) : "l"(v)); return r;
}
// 16B shared load -> two aligned f32x2 pairs (no pack MOVs possible)
__device__ __forceinline__ void lds2(ull& a, ull& b, unsigned addr) {
    asm("ld.shared.v2.b64 {%0, %1}, [%2];" : "=l"(a), "=l"(b) : "r"(addr));
}
__device__ __forceinline__ unsigned s2u(const void* p) {
    unsigned a;
    asm("{ .reg .u64 t; cvta.to.shared.u64 t, %1; cvt.u32.u64 %0, t; }"
        : "=r"(a) : "l"(p));
    return a;
}

struct __align__(16) Smem {
    float4 wst[IDIM * WST_STRIDE];     // 128 rows x 33 float4 = 67584 B
    float  xp[TOK_PER_BLK][XPAD];      // 12288 B
    float  xa[TOK_PER_BLK][IDIM];      // x_attn, token-major, 4096 B
    float  h[TOK_PER_BLK][HROW];       // hidden, token-major, 8448 B
    float  yres[TOK_PER_BLK][IDIM];    // 4096 B
    float  red[8];
    float  red2[8];
    unsigned char ymask[TOK_PER_BLK][IDIM];  // 1024 B
};

extern __shared__ unsigned char smem_raw[];

__global__ void __launch_bounds__(NTHREADS, 2)
net_main_kernel(const float* __restrict__ x, const float* __restrict__ y,
                const float* __restrict__ w1, const float* __restrict__ b1,
                const float* __restrict__ w2, const float* __restrict__ b2)
{
    Smem& sm = *reinterpret_cast<Smem*>(smem_raw);
    const int tid  = threadIdx.x;
    const int lane = tid & 31;
    const int wid  = tid >> 5;
    const int blk  = blockIdx.x;
    const int tok0 = blk * TOK_PER_BLK;

    // ---- zero padded x buffer ----
    for (int e = tid; e < TOK_PER_BLK * XPAD; e += NTHREADS)
        (&sm.xp[0][0])[e] = 0.f;
    __syncthreads();

    // ---- load x, y, mask; count unmasked ----
    float cnt = 0.f;
    for (int e = tid; e < TOK_PER_BLK * IDIM; e += NTHREADS) {
        int m = e >> 7, d = e & 127;
        sm.xp[m][127 + d] = x[(tok0 + m) * IDIM + d];
        float yv = y[(tok0 + m) * IDIM + d];
        sm.yres[m][d] = yv;
        unsigned char msk = (yv == 10000.0f) ? 1 : 0;
        sm.ymask[m][d] = msk;
        cnt += msk ? 0.f : 1.f;
    }

    float sqacc = 0.f;
    const int o = tid & 127;    // channel within chunk (B) / output channel (C)
    const int g = tid >> 7;     // token group: tokens 4g..4g+3

    // shared-space byte addresses for packed GEMM loads
    const unsigned wrow_a = s2u(&sm.wst[o * WST_STRIDE]);
    unsigned xa_a[4], h_a[4];
    #pragma unroll
    for (int t = 0; t < 4; ++t) {
        xa_a[t] = s2u(&sm.xa[4 * g + t][0]);
        h_a[t]  = s2u(&sm.h[4 * g + t][0]);
    }

    for (int it = 0; it < NITER; ++it) {
        __syncthreads();   // yres/xp stable for phase A

        // ================= Phase A: per-warp token pipeline (scalar, exact) =====
        {
            const int m = wid;
            float* xpm = sm.xp[m];
            const float*  ym  = sm.yres[m];
            const float4* xp4 = reinterpret_cast<const float4*>(xpm);
            const float4* ym4 = reinterpret_cast<const float4*>(ym);

            // ||y_res||
            float ny2 = 0.f;
            #pragma unroll
            for (int j = 0; j < 4; ++j) { float v = ym[lane + 32 * j]; ny2 += v * v; }
            #pragma unroll
            for (int off = 16; off; off >>= 1) ny2 += __shfl_xor_sync(~0u, ny2, off);
            float ny = sqrtf(ny2);

            // banded correlation: lane handles shifts s = 4*lane + 128*b + j
            float num[8], dn[8];
            #pragma unroll
            for (int k = 0; k < 8; ++k) { num[k] = 0.f; dn[k] = 0.f; }
            #pragma unroll
            for (int b = 0; b < 2; ++b) {
                int q0 = lane + 32 * b;
                float4 xcur = xp4[q0];
                #pragma unroll 8
                for (int d4 = 0; d4 < 32; ++d4) {
                    float4 yv  = ym4[d4];
                    float4 xnx = xp4[q0 + d4 + 1];
                    float xq[8] = {xcur.x, xcur.y, xcur.z, xcur.w,
                                   xnx.x,  xnx.y,  xnx.z,  xnx.w};
                    #pragma unroll
                    for (int j = 0; j < 4; ++j) {
                        int kk = 4 * b + j;
                        float n = num[kk], q = dn[kk];
                        n = fmaf(yv.x, xq[j    ], n); q = fmaf(xq[j    ], xq[j    ], q);
                        n = fmaf(yv.y, xq[j + 1], n); q = fmaf(xq[j + 1], xq[j + 1], q);
                        n = fmaf(yv.z, xq[j + 2], n); q = fmaf(xq[j + 2], xq[j + 2], q);
                        n = fmaf(yv.w, xq[j + 3], n); q = fmaf(xq[j + 3], xq[j + 3], q);
                        num[kk] = n; dn[kk] = q;
                    }
                    xcur = xnx;
                }
            }

            // first-max (ascending s within lane), then warp first-max
            float best = -INFINITY; int bs = 0x7fffffff;
            #pragma unroll
            for (int b = 0; b < 2; ++b)
            #pragma unroll
            for (int j = 0; j < 4; ++j) {
                int s = 4 * lane + 128 * b + j;
                if (s < 255) {
                    int kk = 4 * b + j;
                    float den = ny * sqrtf(dn[kk]);
                    float sim = (den == 0.f) ? 0.f : num[kk] / den;
                    if (sim > best) { best = sim; bs = s; }
                }
            }
            #pragma unroll
            for (int off = 16; off; off >>= 1) {
                float ob = __shfl_xor_sync(~0u, best, off);
                int   os = __shfl_xor_sync(~0u, bs,   off);
                if (ob > best || (ob == best && os < bs)) { best = ob; bs = os; }
            }
            const int idx = bs;

            // softmax attention: z = x_aug * y_res
            float xav[4], z[4];
            float zmax = -INFINITY;
            #pragma unroll
            for (int j = 0; j < 4; ++j) {
                int d = lane + 32 * j;
                xav[j] = xpm[idx + d];
                z[j]   = xav[j] * ym[d];
                zmax   = fmaxf(zmax, z[j]);
            }
            #pragma unroll
            for (int off = 16; off; off >>= 1) zmax = fmaxf(zmax, __shfl_xor_sync(~0u, zmax, off));
            float es = 0.f, e[4];
            #pragma unroll
            for (int j = 0; j < 4; ++j) { e[j] = expf(z[j] - zmax); es += e[j]; }
            #pragma unroll
            for (int off = 16; off; off >>= 1) es += __shfl_xor_sync(~0u, es, off);
            #pragma unroll
            for (int j = 0; j < 4; ++j) {
                int d = lane + 32 * j;
                sm.xa[m][d] = xav[j] * (e[j] / es);
            }
            __syncwarp();
            // reverse shift: x_res[d] -= x_attn[d + 127 - idx]
            #pragma unroll
            for (int j = 0; j < 4; ++j) {
                int d = lane + 32 * j;
                int src = d + 127 - idx;
                float xe = (src >= 0 && src < 128) ? sm.xa[m][src] : 0.f;
                xpm[127 + d] -= xe;
            }
        }
        __syncthreads();   // xa ready; xp updates done

        // ================= Phase B: h = x_attn @ W1_slice^T + b1 (packed) ======
        for (int chunk = 0; chunk < 2; ++chunk) {
            const float4* wg = reinterpret_cast<const float4*>(
                w1 + (size_t)(it * 256 + chunk * 128) * IDIM);
            #pragma unroll
            for (int r = 0; r < 16; ++r) {
                int j   = tid + r * 256;
                int row = j >> 5;
                int c4  = j & 31;
                sm.wst[row * WST_STRIDE + c4] = wg[j];
            }
            __syncthreads();

            float bv = b1[it * 256 + chunk * 128 + o];
            ull acc[4];
            acc[0] = pk(bv, 0.f); acc[1] = pk(bv, 0.f);
            acc[2] = pk(bv, 0.f); acc[3] = pk(bv, 0.f);
            #pragma unroll 8
            for (int d4 = 0; d4 < 32; ++d4) {
                ull w01, w23;
                lds2(w01, w23, wrow_a + d4 * 16);
                #pragma unroll
                for (int t = 0; t < 4; ++t) {
                    ull x01, x23;
                    lds2(x01, x23, xa_a[t] + d4 * 16);
                    fma2(acc[t], w01, x01);
                    fma2(acc[t], w23, x23);
                }
            }
            #pragma unroll
            for (int t = 0; t < 4; ++t) {
                float2 a = upk(acc[t]);
                sm.h[4 * g + t][chunk * 128 + o] = a.x + a.y;
            }
            __syncthreads();
        }

        // ================= Phase C: y_ele = h @ W2_slice^T + b2 (packed) =======
        float b2v = b2[o];
        ull accc[4];
        accc[0] = pk(b2v, 0.f); accc[1] = pk(b2v, 0.f);
        accc[2] = pk(b2v, 0.f); accc[3] = pk(b2v, 0.f);
        for (int chunk = 0; chunk < 2; ++chunk) {
            const float4* wg2 = reinterpret_cast<const float4*>(w2);
            #pragma unroll
            for (int r = 0; r < 16; ++r) {
                int j   = tid + r * 256;
                int row = j >> 5;
                int c4  = j & 31;
                sm.wst[row * WST_STRIDE + c4] =
                    wg2[(size_t)row * (HDIM / 4) + it * 64 + chunk * 32 + c4];
            }
            __syncthreads();

            const unsigned hoff = chunk * 512;   // chunk*128 floats
            #pragma unroll 8
            for (int c4 = 0; c4 < 32; ++c4) {
                ull w01, w23;
                lds2(w01, w23, wrow_a + c4 * 16);
                #pragma unroll
                for (int t = 0; t < 4; ++t) {
                    ull h01, h23;
                    lds2(h01, h23, h_a[t] + hoff + c4 * 16);
                    fma2(accc[t], w01, h01);
                    fma2(accc[t], w23, h23);
                }
            }
            if (chunk == 0) __syncthreads();   // before restaging wst
        }

        // ---- masked squared error + y_res update ----
        #pragma unroll
        for (int t = 0; t < 4; ++t) {
            int m = 4 * g + t;
            float2 c2 = upk(accc[t]);
            float ye = c2.x + c2.y;
            float yr = sm.yres[m][o];
            if (!sm.ymask[m][o]) { float dd = ye - yr; sqacc += dd * dd; }
            sm.yres[m][o] = yr - ye;
        }
        // next-iteration top __syncthreads orders these writes before phase A
    }

    // ---- block reduction ----
    #pragma unroll
    for (int off = 16; off; off >>= 1) {
        sqacc += __shfl_xor_sync(~0u, sqacc, off);
        cnt   += __shfl_xor_sync(~0u, cnt,   off);
    }
    if (lane == 0) { sm.red[wid] = sqacc; sm.red2[wid] = cnt; }
    __syncthreads();
    if (tid == 0) {
        float s = 0.f, c = 0.f;
        #pragma unroll
        for (int w = 0; w < 8; ++w) { s += sm.red[w]; c += sm.red2[w]; }
        g_psum[blk] = s;
        g_pcnt[blk] = c;
    }
}

__global__ void net_final_kernel(float* __restrict__ out)
{
    __shared__ float ss[NBLK];
    __shared__ float sc[NBLK];
    int t = threadIdx.x;
    ss[t] = g_psum[t];
    sc[t] = g_pcnt[t];
    __syncthreads();
    for (int off = 128; off; off >>= 1) {
        if (t < off) { ss[t] += ss[t + off]; sc[t] += sc[t + off]; }
        __syncthreads();
    }
    if (t == 0) out[0] = ss[0] / (4.0f * sc[0]);
}

// Parity kernels: shift launch sequence so ncu (-s 5 -c 1) captures the MAIN
// kernel at global launch #6 (sequence: dummy, main, final, dummy2 -> main at
// positions 2, 6, 10, ...). Removable once profiling data is in hand.
__global__ void net_parity_a_kernel() {}
__global__ void net_parity_b_kernel() {}

extern "C" void kernel_launch(void* const* d_in, const int* in_sizes, int n_in,
                              void* d_out, int out_size)
{
    (void)in_sizes; (void)n_in; (void)out_size;
    const float* x  = (const float*)d_in[0];
    const float* y  = (const float*)d_in[1];
    const float* w1 = (const float*)d_in[2];
    const float* b1 = (const float*)d_in[3];
    const float* w2 = (const float*)d_in[4];
    const float* b2 = (const float*)d_in[5];
    float* out = (float*)d_out;

    cudaFuncSetAttribute(net_main_kernel,
                         cudaFuncAttributeMaxDynamicSharedMemorySize,
                         (int)sizeof(Smem));
    net_parity_a_kernel<<<1, 32>>>();
    net_main_kernel<<<NBLK, NTHREADS, sizeof(Smem)>>>(x, y, w1, b1, w2, b2);
    net_final_kernel<<<1, NBLK>>>(out);
    net_parity_b_kernel<<<1, 32>>>();
}

// round 7
// speedup vs baseline: 1.1119x; 1.0408x over previous
#include <cuda_runtime.h>
#include <math.h>

#define IDIM 128
#define HDIM 1024
#define NITER 4
#define NTOK 2048
#define TOK_PER_BLK 8
#define NBLK (NTOK / TOK_PER_BLK)   // 256
#define NTHREADS 256
#define XPAD 384            // padded x_res (data at [127,254], zeros elsewhere)
#define WST_STRIDE 33       // float4 stride per staged weight row (conflict-free)
#define HROW 264            // h row stride in floats (16B-aligned rows)
#define PROW 388            // prefix-sum row stride (16B-aligned)

typedef unsigned long long ull;

__device__ float g_psum[NBLK];
__device__ float g_pcnt[NBLK];

// ---- packed fp32x2 helpers ----
__device__ __forceinline__ ull pk(float lo, float hi) {
    ull r; asm("mov.b64 %0, {%1, %2};" : "=l"(r) : "f"(lo), "f"(hi)); return r;
}
__device__ __forceinline__ void fma2(ull& acc, ull a, ull b) {
    asm("fma.rn.f32x2 %0, %1, %2, %3;" : "=l"(acc) : "l"(a), "l"(b), "l"(acc));
}
__device__ __forceinline__ float2 upk(ull v) {
    float2 r; asm("mov.b64 {%0, %1}, %2;" : "=f"(r.x), "=f"(r.y) : "l"(v)); return r;
}
// 16B shared load -> two aligned f32x2 pairs (no pack MOVs)
__device__ __forceinline__ void lds2(ull& a, ull& b, unsigned addr) {
    asm("ld.shared.v2.b64 {%0, %1}, [%2];" : "=l"(a), "=l"(b) : "r"(addr));
}
__device__ __forceinline__ unsigned s2u(const void* p) {
    unsigned a;
    asm("{ .reg .u64 t; cvta.to.shared.u64 t, %1; cvt.u32.u64 %0, t; }"
        : "=r"(a) : "l"(p));
    return a;
}

struct __align__(16) Smem {
    float4 wst[IDIM * WST_STRIDE];     // 67584 B
    float  xp[TOK_PER_BLK][XPAD];      // 12288 B
    float  xa[TOK_PER_BLK][IDIM];      // 4096 B
    union {                            // disjoint live ranges:
        float h[TOK_PER_BLK][HROW];    //   h: phases B/C
        float P[TOK_PER_BLK][PROW];    //   P: phase A prefix sums, 12416 B
    } u;
    float  yres[TOK_PER_BLK][IDIM];    // 4096 B
    float  red[8];
    float  red2[8];
    unsigned char ymask[TOK_PER_BLK][IDIM];  // 1024 B
};

extern __shared__ unsigned char smem_raw[];

__global__ void __launch_bounds__(NTHREADS, 2)
net_main_kernel(const float* __restrict__ x, const float* __restrict__ y,
                const float* __restrict__ w1, const float* __restrict__ b1,
                const float* __restrict__ w2, const float* __restrict__ b2)
{
    Smem& sm = *reinterpret_cast<Smem*>(smem_raw);
    const int tid  = threadIdx.x;
    const int lane = tid & 31;
    const int wid  = tid >> 5;
    const int blk  = blockIdx.x;
    const int tok0 = blk * TOK_PER_BLK;

    // ---- zero padded x buffer ----
    for (int e = tid; e < TOK_PER_BLK * XPAD; e += NTHREADS)
        (&sm.xp[0][0])[e] = 0.f;
    __syncthreads();

    // ---- load x, y, mask; count unmasked ----
    float cnt = 0.f;
    for (int e = tid; e < TOK_PER_BLK * IDIM; e += NTHREADS) {
        int m = e >> 7, d = e & 127;
        sm.xp[m][127 + d] = x[(tok0 + m) * IDIM + d];
        float yv = y[(tok0 + m) * IDIM + d];
        sm.yres[m][d] = yv;
        unsigned char msk = (yv == 10000.0f) ? 1 : 0;
        sm.ymask[m][d] = msk;
        cnt += msk ? 0.f : 1.f;
    }

    float sqacc = 0.f;
    const int o = tid & 127;
    const int g = tid >> 7;

    const unsigned wrow_a = s2u(&sm.wst[o * WST_STRIDE]);
    unsigned xa_a[4], h_a[4];
    #pragma unroll
    for (int t = 0; t < 4; ++t) {
        xa_a[t] = s2u(&sm.xa[4 * g + t][0]);
        h_a[t]  = s2u(&sm.u.h[4 * g + t][0]);
    }

    for (int it = 0; it < NITER; ++it) {
        __syncthreads();   // yres/xp stable; prior-iter h reads done

        // ================= Phase A: per-warp token pipeline =================
        {
            const int m = wid;
            float* xpm = sm.xp[m];
            const float*  ym  = sm.yres[m];
            const float4* xp4 = reinterpret_cast<const float4*>(xpm);
            const float4* ym4 = reinterpret_cast<const float4*>(ym);
            float* Pm = sm.u.P[m];

            // ---- prefix sums of squares: P[i] = sum_{k<i} xp[k]^2 ----
            {
                const float4* b3 = xp4 + lane * 3;
                float4 a = b3[0], b = b3[1], c = b3[2];
                float s[12];
                s[0]  = a.x * a.x;
                s[1]  = fmaf(a.y, a.y, s[0]);
                s[2]  = fmaf(a.z, a.z, s[1]);
                s[3]  = fmaf(a.w, a.w, s[2]);
                s[4]  = fmaf(b.x, b.x, s[3]);
                s[5]  = fmaf(b.y, b.y, s[4]);
                s[6]  = fmaf(b.z, b.z, s[5]);
                s[7]  = fmaf(b.w, b.w, s[6]);
                s[8]  = fmaf(c.x, c.x, s[7]);
                s[9]  = fmaf(c.y, c.y, s[8]);
                s[10] = fmaf(c.z, c.z, s[9]);
                s[11] = fmaf(c.w, c.w, s[10]);
                float incl = s[11];
                #pragma unroll
                for (int off = 1; off < 32; off <<= 1) {
                    float t = __shfl_up_sync(~0u, incl, off);
                    if (lane >= off) incl += t;
                }
                float excl = incl - s[11];
                if (lane == 0) Pm[0] = 0.f;
                #pragma unroll
                for (int j = 0; j < 12; ++j)
                    Pm[lane * 12 + j + 1] = excl + s[j];
            }

            // ||y_res||
            float ny2 = 0.f;
            #pragma unroll
            for (int j = 0; j < 4; ++j) { float v = ym[lane + 32 * j]; ny2 += v * v; }
            #pragma unroll
            for (int off = 16; off; off >>= 1) ny2 += __shfl_xor_sync(~0u, ny2, off);
            float ny = sqrtf(ny2);
            __syncwarp();   // P visible to all lanes

            // banded correlation (num only): shifts s = 4*lane + 128*b + j
            float num[8];
            #pragma unroll
            for (int k = 0; k < 8; ++k) num[k] = 0.f;
            #pragma unroll
            for (int b = 0; b < 2; ++b) {
                int q0 = lane + 32 * b;
                float4 xcur = xp4[q0];
                #pragma unroll 8
                for (int d4 = 0; d4 < 32; ++d4) {
                    float4 yv  = ym4[d4];
                    float4 xnx = xp4[q0 + d4 + 1];
                    float xq[8] = {xcur.x, xcur.y, xcur.z, xcur.w,
                                   xnx.x,  xnx.y,  xnx.z,  xnx.w};
                    #pragma unroll
                    for (int j = 0; j < 4; ++j) {
                        int kk = 4 * b + j;
                        float n = num[kk];
                        n = fmaf(yv.x, xq[j    ], n);
                        n = fmaf(yv.y, xq[j + 1], n);
                        n = fmaf(yv.z, xq[j + 2], n);
                        n = fmaf(yv.w, xq[j + 3], n);
                        num[kk] = n;
                    }
                    xcur = xnx;
                }
            }

            // per-lane first-max using prefix-difference window norms
            const float4* P4m = reinterpret_cast<const float4*>(Pm);
            float best = -INFINITY; int bs = 0x7fffffff;
            #pragma unroll
            for (int b = 0; b < 2; ++b) {
                float4 Plo = P4m[lane + 32 * b];
                float4 Phi = P4m[lane + 32 * (b + 1)];
                float dnv[4] = {fmaxf(Phi.x - Plo.x, 0.f),
                                fmaxf(Phi.y - Plo.y, 0.f),
                                fmaxf(Phi.z - Plo.z, 0.f),
                                fmaxf(Phi.w - Plo.w, 0.f)};
                #pragma unroll
                for (int j = 0; j < 4; ++j) {
                    int s = 4 * lane + 128 * b + j;
                    if (s < 255) {
                        float den = ny * sqrtf(dnv[j]);
                        float sim = (den == 0.f) ? 0.f : num[4 * b + j] / den;
                        if (sim > best) { best = sim; bs = s; }
                    }
                }
            }
            #pragma unroll
            for (int off = 16; off; off >>= 1) {
                float ob = __shfl_xor_sync(~0u, best, off);
                int   os = __shfl_xor_sync(~0u, bs,   off);
                if (ob > best || (ob == best && os < bs)) { best = ob; bs = os; }
            }
            const int idx = bs;

            // softmax attention: z = x_aug * y_res
            float xav[4], z[4];
            float zmax = -INFINITY;
            #pragma unroll
            for (int j = 0; j < 4; ++j) {
                int d = lane + 32 * j;
                xav[j] = xpm[idx + d];
                z[j]   = xav[j] * ym[d];
                zmax   = fmaxf(zmax, z[j]);
            }
            #pragma unroll
            for (int off = 16; off; off >>= 1) zmax = fmaxf(zmax, __shfl_xor_sync(~0u, zmax, off));
            float es = 0.f, e[4];
            #pragma unroll
            for (int j = 0; j < 4; ++j) { e[j] = expf(z[j] - zmax); es += e[j]; }
            #pragma unroll
            for (int off = 16; off; off >>= 1) es += __shfl_xor_sync(~0u, es, off);
            #pragma unroll
            for (int j = 0; j < 4; ++j) {
                int d = lane + 32 * j;
                sm.xa[m][d] = xav[j] * (e[j] / es);
            }
            __syncwarp();
            // reverse shift: x_res[d] -= x_attn[d + 127 - idx]
            #pragma unroll
            for (int j = 0; j < 4; ++j) {
                int d = lane + 32 * j;
                int src = d + 127 - idx;
                float xe = (src >= 0 && src < 128) ? sm.xa[m][src] : 0.f;
                xpm[127 + d] -= xe;
            }
        }
        __syncthreads();   // xa ready; xp/P done (P dead after this point)

        // ================= Phase B: h = x_attn @ W1_slice^T + b1 ===========
        for (int chunk = 0; chunk < 2; ++chunk) {
            const float4* wg = reinterpret_cast<const float4*>(
                w1 + (size_t)(it * 256 + chunk * 128) * IDIM);
            #pragma unroll
            for (int r = 0; r < 16; ++r) {
                int j   = tid + r * 256;
                int row = j >> 5;
                int c4  = j & 31;
                sm.wst[row * WST_STRIDE + c4] = wg[j];
            }
            __syncthreads();

            float bv = b1[it * 256 + chunk * 128 + o];
            ull acc[4];
            acc[0] = pk(bv, 0.f); acc[1] = pk(bv, 0.f);
            acc[2] = pk(bv, 0.f); acc[3] = pk(bv, 0.f);
            #pragma unroll 8
            for (int d4 = 0; d4 < 32; ++d4) {
                ull w01, w23;
                lds2(w01, w23, wrow_a + d4 * 16);
                #pragma unroll
                for (int t = 0; t < 4; ++t) {
                    ull x01, x23;
                    lds2(x01, x23, xa_a[t] + d4 * 16);
                    fma2(acc[t], w01, x01);
                    fma2(acc[t], w23, x23);
                }
            }
            #pragma unroll
            for (int t = 0; t < 4; ++t) {
                float2 a = upk(acc[t]);
                sm.u.h[4 * g + t][chunk * 128 + o] = a.x + a.y;
            }
            __syncthreads();
        }

        // ================= Phase C: y_ele = h @ W2_slice^T + b2 ============
        float b2v = b2[o];
        ull accc[4];
        accc[0] = pk(b2v, 0.f); accc[1] = pk(b2v, 0.f);
        accc[2] = pk(b2v, 0.f); accc[3] = pk(b2v, 0.f);
        for (int chunk = 0; chunk < 2; ++chunk) {
            const float4* wg2 = reinterpret_cast<const float4*>(w2);
            #pragma unroll
            for (int r = 0; r < 16; ++r) {
                int j   = tid + r * 256;
                int row = j >> 5;
                int c4  = j & 31;
                sm.wst[row * WST_STRIDE + c4] =
                    wg2[(size_t)row * (HDIM / 4) + it * 64 + chunk * 32 + c4];
            }
            __syncthreads();

            const unsigned hoff = chunk * 512;
            #pragma unroll 8
            for (int c4 = 0; c4 < 32; ++c4) {
                ull w01, w23;
                lds2(w01, w23, wrow_a + c4 * 16);
                #pragma unroll
                for (int t = 0; t < 4; ++t) {
                    ull h01, h23;
                    lds2(h01, h23, h_a[t] + hoff + c4 * 16);
                    fma2(accc[t], w01, h01);
                    fma2(accc[t], w23, h23);
                }
            }
            if (chunk == 0) __syncthreads();
        }

        // ---- masked squared error + y_res update ----
        #pragma unroll
        for (int t = 0; t < 4; ++t) {
            int m = 4 * g + t;
            float2 c2 = upk(accc[t]);
            float ye = c2.x + c2.y;
            float yr = sm.yres[m][o];
            if (!sm.ymask[m][o]) { float dd = ye - yr; sqacc += dd * dd; }
            sm.yres[m][o] = yr - ye;
        }
    }

    // ---- block reduction ----
    #pragma unroll
    for (int off = 16; off; off >>= 1) {
        sqacc += __shfl_xor_sync(~0u, sqacc, off);
        cnt   += __shfl_xor_sync(~0u, cnt,   off);
    }
    if (lane == 0) { sm.red[wid] = sqacc; sm.red2[wid] = cnt; }
    __syncthreads();
    if (tid == 0) {
        float s = 0.f, c = 0.f;
        #pragma unroll
        for (int w = 0; w < 8; ++w) { s += sm.red[w]; c += sm.red2[w]; }
        g_psum[blk] = s;
        g_pcnt[blk] = c;
    }
}

__global__ void net_final_kernel(float* __restrict__ out)
{
    __shared__ float ss[NBLK];
    __shared__ float sc[NBLK];
    int t = threadIdx.x;
    ss[t] = g_psum[t];
    sc[t] = g_pcnt[t];
    __syncthreads();
    for (int off = 128; off; off >>= 1) {
        if (t < off) { ss[t] += ss[t + off]; sc[t] += sc[t + off]; }
        __syncthreads();
    }
    if (t == 0) out[0] = ss[0] / (4.0f * sc[0]);
}

extern "C" void kernel_launch(void* const* d_in, const int* in_sizes, int n_in,
                              void* d_out, int out_size)
{
    (void)in_sizes; (void)n_in; (void)out_size;
    const float* x  = (const float*)d_in[0];
    const float* y  = (const float*)d_in[1];
    const float* w1 = (const float*)d_in[2];
    const float* b1 = (const float*)d_in[3];
    const float* w2 = (const float*)d_in[4];
    const float* b2 = (const float*)d_in[5];
    float* out = (float*)d_out;

    cudaFuncSetAttribute(net_main_kernel,
                         cudaFuncAttributeMaxDynamicSharedMemorySize,
                         (int)sizeof(Smem));
    net_main_kernel<<<NBLK, NTHREADS, sizeof(Smem)>>>(x, y, w1, b1, w2, b2);
    net_final_kernel<<<1, NBLK>>>(out);
}

// round 8
// speedup vs baseline: 1.1514x; 1.0355x over previous
#include <cuda_runtime.h>
#include <math.h>

#define IDIM 128
#define HDIM 1024
#define NITER 4
#define NTOK 2048
#define NBLK 148            // one block per SM, perfectly balanced wave
#define NTHREADS 512        // 16 warps
#define TOKMAX 14           // blocks 0..123: 14 tokens, 124..147: 13
#define XPAD 384            // padded x_res (data at [127,254], zeros elsewhere)
#define WST_STRIDE 33       // float4 stride per staged weight row (conflict-free)
#define HROW 264            // h row stride in floats (16B-aligned rows)

typedef unsigned long long ull;

__device__ float g_psum[NBLK];
__device__ float g_pcnt[NBLK];

// ---- packed fp32x2 helpers ----
__device__ __forceinline__ ull pk(float lo, float hi) {
    ull r; asm("mov.b64 %0, {%1, %2};" : "=l"(r) : "f"(lo), "f"(hi)); return r;
}
__device__ __forceinline__ void fma2(ull& acc, ull a, ull b) {
    asm("fma.rn.f32x2 %0, %1, %2, %3;" : "=l"(acc) : "l"(a), "l"(b), "l"(acc));
}
__device__ __forceinline__ float2 upk(ull v) {
    float2 r; asm("mov.b64 {%0, %1}, %2;" : "=f"(r.x), "=f"(r.y) : "l"(v)); return r;
}
// 16B shared load -> two aligned f32x2 pairs (no pack MOVs)
__device__ __forceinline__ void lds2(ull& a, ull& b, unsigned addr) {
    asm("ld.shared.v2.b64 {%0, %1}, [%2];" : "=l"(a), "=l"(b) : "r"(addr));
}
__device__ __forceinline__ unsigned s2u(const void* p) {
    unsigned a;
    asm("{ .reg .u64 t; cvta.to.shared.u64 t, %1; cvt.u32.u64 %0, t; }"
        : "=r"(a) : "l"(p));
    return a;
}

struct __align__(16) Smem {
    float4 wst[IDIM * WST_STRIDE];     // 67584 B
    float  xp[TOKMAX][XPAD];           // 21504 B
    float  xa[TOKMAX][IDIM];           // 7168 B
    float  h[TOKMAX][HROW];            // 14784 B
    float  yres[TOKMAX][IDIM];         // 7168 B
    float  red[16];
    float  red2[16];
    unsigned char ymask[TOKMAX][IDIM]; // 1792 B
};

extern __shared__ unsigned char smem_raw[];

__global__ void __launch_bounds__(NTHREADS, 1)
net_main_kernel(const float* __restrict__ x, const float* __restrict__ y,
                const float* __restrict__ w1, const float* __restrict__ b1,
                const float* __restrict__ w2, const float* __restrict__ b2)
{
    Smem& sm = *reinterpret_cast<Smem*>(smem_raw);
    const int tid  = threadIdx.x;
    const int lane = tid & 31;
    const int wid  = tid >> 5;
    const int blk  = blockIdx.x;
    // token partition: blocks 0..123 get 14, blocks 124..147 get 13
    const int tcnt = (blk < 124) ? 14 : 13;
    const int tok0 = (blk < 124) ? blk * 14 : 124 * 14 + (blk - 124) * 13;

    // ---- zero padded x buffer (all TOKMAX rows) ----
    for (int e = tid; e < TOKMAX * XPAD; e += NTHREADS)
        (&sm.xp[0][0])[e] = 0.f;
    __syncthreads();

    // ---- load x, y, mask; count unmasked (valid tokens only) ----
    float cnt = 0.f;
    for (int e = tid; e < tcnt * IDIM; e += NTHREADS) {
        int m = e >> 7, d = e & 127;
        sm.xp[m][127 + d] = x[(tok0 + m) * IDIM + d];
        float yv = y[(tok0 + m) * IDIM + d];
        sm.yres[m][d] = yv;
        unsigned char msk = (yv == 10000.0f) ? 1 : 0;
        sm.ymask[m][d] = msk;
        cnt += msk ? 0.f : 1.f;
    }

    float sqacc = 0.f;
    const int o = tid & 127;     // channel within chunk / output channel
    const int g = tid >> 7;      // token-slot group: slots g, g+4, g+8, g+12

    int   slot[4];
    bool  sv[4];
    #pragma unroll
    for (int t = 0; t < 4; ++t) { slot[t] = g + 4 * t; sv[t] = slot[t] < tcnt; }

    const unsigned wrow_a = s2u(&sm.wst[o * WST_STRIDE]);
    unsigned xa_a[4], h_a[4];
    #pragma unroll
    for (int t = 0; t < 4; ++t) {
        int s = sv[t] ? slot[t] : 0;      // clamp invalid to slot 0 (reads only)
        xa_a[t] = s2u(&sm.xa[s][0]);
        h_a[t]  = s2u(&sm.h[s][0]);
    }

    for (int it = 0; it < NITER; ++it) {
        __syncthreads();   // yres/xp stable for phase A

        // ================= Phase A: per-warp token pipeline =================
        if (wid < tcnt) {
            const int m = wid;
            float* xpm = sm.xp[m];
            const float*  ym  = sm.yres[m];
            const float4* xp4 = reinterpret_cast<const float4*>(xpm);
            const float4* ym4 = reinterpret_cast<const float4*>(ym);

            // ||y_res||
            float ny2 = 0.f;
            #pragma unroll
            for (int j = 0; j < 4; ++j) { float v = ym[lane + 32 * j]; ny2 += v * v; }
            #pragma unroll
            for (int off = 16; off; off >>= 1) ny2 += __shfl_xor_sync(~0u, ny2, off);
            float ny = sqrtf(ny2);

            // banded correlation: lane handles shifts s = 4*lane + 128*b + j
            float num[8], dn[8];
            #pragma unroll
            for (int k = 0; k < 8; ++k) { num[k] = 0.f; dn[k] = 0.f; }
            #pragma unroll
            for (int b = 0; b < 2; ++b) {
                int q0 = lane + 32 * b;
                float4 xcur = xp4[q0];
                #pragma unroll 8
                for (int d4 = 0; d4 < 32; ++d4) {
                    float4 yv  = ym4[d4];
                    float4 xnx = xp4[q0 + d4 + 1];
                    float xq[8] = {xcur.x, xcur.y, xcur.z, xcur.w,
                                   xnx.x,  xnx.y,  xnx.z,  xnx.w};
                    #pragma unroll
                    for (int j = 0; j < 4; ++j) {
                        int kk = 4 * b + j;
                        float n = num[kk], q = dn[kk];
                        n = fmaf(yv.x, xq[j    ], n); q = fmaf(xq[j    ], xq[j    ], q);
                        n = fmaf(yv.y, xq[j + 1], n); q = fmaf(xq[j + 1], xq[j + 1], q);
                        n = fmaf(yv.z, xq[j + 2], n); q = fmaf(xq[j + 2], xq[j + 2], q);
                        n = fmaf(yv.w, xq[j + 3], n); q = fmaf(xq[j + 3], xq[j + 3], q);
                        num[kk] = n; dn[kk] = q;
                    }
                    xcur = xnx;
                }
            }

            // first-max (ascending s within lane), then warp first-max
            float best = -INFINITY; int bs = 0x7fffffff;
            #pragma unroll
            for (int b = 0; b < 2; ++b)
            #pragma unroll
            for (int j = 0; j < 4; ++j) {
                int s = 4 * lane + 128 * b + j;
                if (s < 255) {
                    int kk = 4 * b + j;
                    float den = ny * sqrtf(dn[kk]);
                    float sim = (den == 0.f) ? 0.f : num[kk] / den;
                    if (sim > best) { best = sim; bs = s; }
                }
            }
            #pragma unroll
            for (int off = 16; off; off >>= 1) {
                float ob = __shfl_xor_sync(~0u, best, off);
                int   os = __shfl_xor_sync(~0u, bs,   off);
                if (ob > best || (ob == best && os < bs)) { best = ob; bs = os; }
            }
            const int idx = bs;

            // softmax attention: z = x_aug * y_res
            float xav[4], z[4];
            float zmax = -INFINITY;
            #pragma unroll
            for (int j = 0; j < 4; ++j) {
                int d = lane + 32 * j;
                xav[j] = xpm[idx + d];
                z[j]   = xav[j] * ym[d];
                zmax   = fmaxf(zmax, z[j]);
            }
            #pragma unroll
            for (int off = 16; off; off >>= 1) zmax = fmaxf(zmax, __shfl_xor_sync(~0u, zmax, off));
            float es = 0.f, e[4];
            #pragma unroll
            for (int j = 0; j < 4; ++j) { e[j] = expf(z[j] - zmax); es += e[j]; }
            #pragma unroll
            for (int off = 16; off; off >>= 1) es += __shfl_xor_sync(~0u, es, off);
            #pragma unroll
            for (int j = 0; j < 4; ++j) {
                int d = lane + 32 * j;
                sm.xa[m][d] = xav[j] * (e[j] / es);
            }
            __syncwarp();
            // reverse shift: x_res[d] -= x_attn[d + 127 - idx]
            #pragma unroll
            for (int j = 0; j < 4; ++j) {
                int d = lane + 32 * j;
                int src = d + 127 - idx;
                float xe = (src >= 0 && src < 128) ? sm.xa[m][src] : 0.f;
                xpm[127 + d] -= xe;
            }
        }
        __syncthreads();   // xa ready; xp updates done

        // ================= Phase B: h = x_attn @ W1_slice^T + b1 ===========
        for (int chunk = 0; chunk < 2; ++chunk) {
            const float4* wg = reinterpret_cast<const float4*>(
                w1 + (size_t)(it * 256 + chunk * 128) * IDIM);
            #pragma unroll
            for (int r = 0; r < 8; ++r) {
                int j   = tid + r * 512;       // 0..4095
                int row = j >> 5;
                int c4  = j & 31;
                sm.wst[row * WST_STRIDE + c4] = wg[j];
            }
            __syncthreads();

            float bv = b1[it * 256 + chunk * 128 + o];
            ull acc[4];
            acc[0] = pk(bv, 0.f); acc[1] = pk(bv, 0.f);
            acc[2] = pk(bv, 0.f); acc[3] = pk(bv, 0.f);
            #pragma unroll 8
            for (int d4 = 0; d4 < 32; ++d4) {
                ull w01, w23;
                lds2(w01, w23, wrow_a + d4 * 16);
                #pragma unroll
                for (int t = 0; t < 4; ++t) {
                    ull x01, x23;
                    lds2(x01, x23, xa_a[t] + d4 * 16);
                    fma2(acc[t], w01, x01);
                    fma2(acc[t], w23, x23);
                }
            }
            #pragma unroll
            for (int t = 0; t < 4; ++t) {
                if (sv[t]) {
                    float2 a = upk(acc[t]);
                    sm.h[slot[t]][chunk * 128 + o] = a.x + a.y;
                }
            }
            __syncthreads();
        }

        // ================= Phase C: y_ele = h @ W2_slice^T + b2 ============
        float b2v = b2[o];
        ull accc[4];
        accc[0] = pk(b2v, 0.f); accc[1] = pk(b2v, 0.f);
        accc[2] = pk(b2v, 0.f); accc[3] = pk(b2v, 0.f);
        for (int chunk = 0; chunk < 2; ++chunk) {
            const float4* wg2 = reinterpret_cast<const float4*>(w2);
            #pragma unroll
            for (int r = 0; r < 8; ++r) {
                int j   = tid + r * 512;
                int row = j >> 5;
                int c4  = j & 31;
                sm.wst[row * WST_STRIDE + c4] =
                    wg2[(size_t)row * (HDIM / 4) + it * 64 + chunk * 32 + c4];
            }
            __syncthreads();

            const unsigned hoff = chunk * 512;   // chunk*128 floats
            #pragma unroll 8
            for (int c4 = 0; c4 < 32; ++c4) {
                ull w01, w23;
                lds2(w01, w23, wrow_a + c4 * 16);
                #pragma unroll
                for (int t = 0; t < 4; ++t) {
                    ull h01, h23;
                    lds2(h01, h23, h_a[t] + hoff + c4 * 16);
                    fma2(accc[t], w01, h01);
                    fma2(accc[t], w23, h23);
                }
            }
            if (chunk == 0) __syncthreads();   // before restaging wst
        }

        // ---- masked squared error + y_res update ----
        #pragma unroll
        for (int t = 0; t < 4; ++t) {
            if (sv[t]) {
                int m = slot[t];
                float2 c2 = upk(accc[t]);
                float ye = c2.x + c2.y;
                float yr = sm.yres[m][o];
                if (!sm.ymask[m][o]) { float dd = ye - yr; sqacc += dd * dd; }
                sm.yres[m][o] = yr - ye;
            }
        }
        // next-iteration top __syncthreads orders these writes before phase A
    }

    // ---- block reduction ----
    #pragma unroll
    for (int off = 16; off; off >>= 1) {
        sqacc += __shfl_xor_sync(~0u, sqacc, off);
        cnt   += __shfl_xor_sync(~0u, cnt,   off);
    }
    if (lane == 0) { sm.red[wid] = sqacc; sm.red2[wid] = cnt; }
    __syncthreads();
    if (tid == 0) {
        float s = 0.f, c = 0.f;
        #pragma unroll
        for (int w = 0; w < 16; ++w) { s += sm.red[w]; c += sm.red2[w]; }
        g_psum[blk] = s;
        g_pcnt[blk] = c;
    }
}

__global__ void net_final_kernel(float* __restrict__ out)
{
    __shared__ float ss[256];
    __shared__ float sc[256];
    int t = threadIdx.x;
    ss[t] = (t < NBLK) ? g_psum[t] : 0.f;
    sc[t] = (t < NBLK) ? g_pcnt[t] : 0.f;
    __syncthreads();
    for (int off = 128; off; off >>= 1) {
        if (t < off) { ss[t] += ss[t + off]; sc[t] += sc[t + off]; }
        __syncthreads();
    }
    if (t == 0) out[0] = ss[0] / (4.0f * sc[0]);
}

extern "C" void kernel_launch(void* const* d_in, const int* in_sizes, int n_in,
                              void* d_out, int out_size)
{
    (void)in_sizes; (void)n_in; (void)out_size;
    const float* x  = (const float*)d_in[0];
    const float* y  = (const float*)d_in[1];
    const float* w1 = (const float*)d_in[2];
    const float* b1 = (const float*)d_in[3];
    const float* w2 = (const float*)d_in[4];
    const float* b2 = (const float*)d_in[5];
    float* out = (float*)d_out;

    cudaFuncSetAttribute(net_main_kernel,
                         cudaFuncAttributeMaxDynamicSharedMemorySize,
                         (int)sizeof(Smem));
    net_main_kernel<<<NBLK, NTHREADS, sizeof(Smem)>>>(x, y, w1, b1, w2, b2);
    net_final_kernel<<<1, 256>>>(out);
}